// round 4
// baseline (speedup 1.0000x reference)
#include <cuda_runtime.h>
#include <cstdint>

// HI4B1C codebook quantizer, GB300 sm_103a.
// grid[i] = i - 7.5 (i = 0..15). Nearest codeword closed-form:
//   idx = clamp(ceil(x) + 7, 0, 15)   (ceil matches jnp.argmax first-max tie rule)
//   val = idx - 7.5
// Pure HBM-streaming kernel; float4 vectorized.

__device__ __forceinline__ int quant_idx(float x) {
    int i = __float2int_ru(x) + 7;      // ceil(x) + 7, single F2I.U32.RU-style op
    i = max(i, 0);
    i = min(i, 15);
    return i;
}

// Layout A: d_out is float[2N]: [0,N) = vals (f32), [N,2N) = idx cast to float.
__global__ void __launch_bounds__(256)
quant_float_concat(const float4* __restrict__ x,
                   float4* __restrict__ vals,
                   float4* __restrict__ idxf,
                   int n4) {
    int i = blockIdx.x * blockDim.x + threadIdx.x;
    if (i >= n4) return;
    float4 v = x[i];
    int i0 = quant_idx(v.x);
    int i1 = quant_idx(v.y);
    int i2 = quant_idx(v.z);
    int i3 = quant_idx(v.w);
    float4 out_v;
    out_v.x = (float)i0 - 7.5f;
    out_v.y = (float)i1 - 7.5f;
    out_v.z = (float)i2 - 7.5f;
    out_v.w = (float)i3 - 7.5f;
    float4 out_i;
    out_i.x = (float)i0;
    out_i.y = (float)i1;
    out_i.z = (float)i2;
    out_i.w = (float)i3;
    vals[i] = out_v;
    idxf[i] = out_i;
}

// Layout B: d_out raw bytes: first 4N bytes = f32 vals, next N bytes = u8 idx.
__global__ void __launch_bounds__(256)
quant_byte_concat(const float4* __restrict__ x,
                  float4* __restrict__ vals,
                  uchar4* __restrict__ idx8,
                  int n4) {
    int i = blockIdx.x * blockDim.x + threadIdx.x;
    if (i >= n4) return;
    float4 v = x[i];
    int i0 = quant_idx(v.x);
    int i1 = quant_idx(v.y);
    int i2 = quant_idx(v.z);
    int i3 = quant_idx(v.w);
    float4 out_v;
    out_v.x = (float)i0 - 7.5f;
    out_v.y = (float)i1 - 7.5f;
    out_v.z = (float)i2 - 7.5f;
    out_v.w = (float)i3 - 7.5f;
    vals[i] = out_v;
    idx8[i] = make_uchar4((unsigned char)i0, (unsigned char)i1,
                          (unsigned char)i2, (unsigned char)i3);
}

// Layout C: vals only (float[N]).
__global__ void __launch_bounds__(256)
quant_vals_only(const float4* __restrict__ x,
                float4* __restrict__ vals,
                int n4) {
    int i = blockIdx.x * blockDim.x + threadIdx.x;
    if (i >= n4) return;
    float4 v = x[i];
    float4 out_v;
    out_v.x = (float)quant_idx(v.x) - 7.5f;
    out_v.y = (float)quant_idx(v.y) - 7.5f;
    out_v.z = (float)quant_idx(v.z) - 7.5f;
    out_v.w = (float)quant_idx(v.w) - 7.5f;
    vals[i] = out_v;
}

// Scalar tail (handles n % 4 != 0; for N = 8388608 this launches 0 work but
// keeps the kernel shape-robust).
__global__ void quant_tail_float(const float* __restrict__ x,
                                 float* __restrict__ vals,
                                 float* __restrict__ idxf,
                                 int start, int n) {
    int i = start + blockIdx.x * blockDim.x + threadIdx.x;
    if (i >= n) return;
    int q = quant_idx(x[i]);
    vals[i] = (float)q - 7.5f;
    if (idxf) idxf[i] = (float)q;
}

__global__ void quant_tail_byte(const float* __restrict__ x,
                                float* __restrict__ vals,
                                unsigned char* __restrict__ idx8,
                                int start, int n) {
    int i = start + blockIdx.x * blockDim.x + threadIdx.x;
    if (i >= n) return;
    int q = quant_idx(x[i]);
    vals[i] = (float)q - 7.5f;
    idx8[i] = (unsigned char)q;
}

extern "C" void kernel_launch(void* const* d_in, const int* in_sizes, int n_in,
                              void* d_out, int out_size) {
    const float* X = (const float*)d_in[0];   // X is input 0 per reference order
    const int n  = in_sizes[0];               // 8,388,608
    const int n4 = n / 4;
    const int rem = n - n4 * 4;

    const int BS = 256;
    const int nb = (n4 + BS - 1) / BS;

    if (out_size == 2 * n) {
        // float32 concat: [vals | idx-as-float]
        float* vals = (float*)d_out;
        float* idxf = vals + n;
        if (n4 > 0)
            quant_float_concat<<<nb, BS>>>((const float4*)X, (float4*)vals,
                                           (float4*)idxf, n4);
        if (rem > 0)
            quant_tail_float<<<1, 32>>>(X, vals, idxf, n4 * 4, n);
    } else if (out_size == n) {
        // vals only
        float* vals = (float*)d_out;
        if (n4 > 0)
            quant_vals_only<<<nb, BS>>>((const float4*)X, (float4*)vals, n4);
        if (rem > 0)
            quant_tail_float<<<1, 32>>>(X, vals, nullptr, n4 * 4, n);
    } else {
        // byte-packed: first 4N bytes f32 vals, next N bytes u8 idx
        float* vals = (float*)d_out;
        unsigned char* idx8 = (unsigned char*)d_out + (size_t)4 * n;
        if (n4 > 0)
            quant_byte_concat<<<nb, BS>>>((const float4*)X, (float4*)vals,
                                          (uchar4*)idx8, n4);
        if (rem > 0)
            quant_tail_byte<<<1, 32>>>(X, vals, idx8, n4 * 4, n);
    }
}

// round 5
// speedup vs baseline: 1.1530x; 1.1530x over previous
#include <cuda_runtime.h>
#include <cstdint>

// HI4B1C codebook quantizer, GB300 sm_103a.  R4: streaming cache hints + ILP=4.
// grid[i] = i - 7.5 (i = 0..15). Nearest codeword closed-form:
//   idx = clamp(ceil(x) + 7, 0, 15)   (ceil matches jnp.argmax first-max tie rule)
//   val = idx - 7.5
// Pure HBM-streaming kernel: 32MB read + 64MB write, never reread ->
// non-temporal loads/stores (__ldcs/__stcs) + 4 float4 per thread for MLP=4.

__device__ __forceinline__ int quant_idx(float x) {
    int i = __float2int_ru(x) + 7;      // ceil(x) + 7
    i = max(i, 0);
    i = min(i, 15);
    return i;
}

__device__ __forceinline__ void quant_f4(const float4& v, float4& out_v, float4& out_i) {
    int i0 = quant_idx(v.x);
    int i1 = quant_idx(v.y);
    int i2 = quant_idx(v.z);
    int i3 = quant_idx(v.w);
    out_v.x = (float)i0 - 7.5f;  out_i.x = (float)i0;
    out_v.y = (float)i1 - 7.5f;  out_i.y = (float)i1;
    out_v.z = (float)i2 - 7.5f;  out_i.z = (float)i2;
    out_v.w = (float)i3 - 7.5f;  out_i.w = (float)i3;
}

// Layout A (observed: out_size == 2N floats): [0,N) = vals f32, [N,2N) = idx as f32.
// Each thread processes ITER=4 grid-strided float4s; loads front-batched (MLP=4).
__global__ void __launch_bounds__(256)
quant_float_concat_v2(const float4* __restrict__ x,
                      float4* __restrict__ vals,
                      float4* __restrict__ idxf,
                      int n4) {
    const int stride = gridDim.x * blockDim.x;
    const int base = blockIdx.x * blockDim.x + threadIdx.x;

    int i0 = base;
    int i1 = base + stride;
    int i2 = base + 2 * stride;
    int i3 = base + 3 * stride;

    // Fast path: all four in range (true for every thread when n4 % (4*stride)==0).
    if (i3 < n4) {
        float4 v0 = __ldcs(&x[i0]);
        float4 v1 = __ldcs(&x[i1]);
        float4 v2 = __ldcs(&x[i2]);
        float4 v3 = __ldcs(&x[i3]);
        float4 ov0, oi0, ov1, oi1, ov2, oi2, ov3, oi3;
        quant_f4(v0, ov0, oi0);
        quant_f4(v1, ov1, oi1);
        quant_f4(v2, ov2, oi2);
        quant_f4(v3, ov3, oi3);
        __stcs(&vals[i0], ov0);  __stcs(&idxf[i0], oi0);
        __stcs(&vals[i1], ov1);  __stcs(&idxf[i1], oi1);
        __stcs(&vals[i2], ov2);  __stcs(&idxf[i2], oi2);
        __stcs(&vals[i3], ov3);  __stcs(&idxf[i3], oi3);
    } else {
        #pragma unroll
        for (int k = 0; k < 4; k++) {
            int i = base + k * stride;
            if (i < n4) {
                float4 v = __ldcs(&x[i]);
                float4 ov, oi;
                quant_f4(v, ov, oi);
                __stcs(&vals[i], ov);
                __stcs(&idxf[i], oi);
            }
        }
    }
}

// Layout B fallback: first 4N bytes = f32 vals, next N bytes = u8 idx.
__global__ void __launch_bounds__(256)
quant_byte_concat(const float4* __restrict__ x,
                  float4* __restrict__ vals,
                  uchar4* __restrict__ idx8,
                  int n4) {
    int i = blockIdx.x * blockDim.x + threadIdx.x;
    if (i >= n4) return;
    float4 v = __ldcs(&x[i]);
    int i0 = quant_idx(v.x);
    int i1 = quant_idx(v.y);
    int i2 = quant_idx(v.z);
    int i3 = quant_idx(v.w);
    float4 out_v;
    out_v.x = (float)i0 - 7.5f;
    out_v.y = (float)i1 - 7.5f;
    out_v.z = (float)i2 - 7.5f;
    out_v.w = (float)i3 - 7.5f;
    __stcs(&vals[i], out_v);
    idx8[i] = make_uchar4((unsigned char)i0, (unsigned char)i1,
                          (unsigned char)i2, (unsigned char)i3);
}

// Layout C fallback: vals only.
__global__ void __launch_bounds__(256)
quant_vals_only(const float4* __restrict__ x,
                float4* __restrict__ vals,
                int n4) {
    int i = blockIdx.x * blockDim.x + threadIdx.x;
    if (i >= n4) return;
    float4 v = __ldcs(&x[i]);
    float4 out_v;
    out_v.x = (float)quant_idx(v.x) - 7.5f;
    out_v.y = (float)quant_idx(v.y) - 7.5f;
    out_v.z = (float)quant_idx(v.z) - 7.5f;
    out_v.w = (float)quant_idx(v.w) - 7.5f;
    __stcs(&vals[i], out_v);
}

// Scalar tail (n % 4 != 0; zero work for N = 8388608).
__global__ void quant_tail_float(const float* __restrict__ x,
                                 float* __restrict__ vals,
                                 float* __restrict__ idxf,
                                 int start, int n) {
    int i = start + blockIdx.x * blockDim.x + threadIdx.x;
    if (i >= n) return;
    int q = quant_idx(x[i]);
    vals[i] = (float)q - 7.5f;
    if (idxf) idxf[i] = (float)q;
}

__global__ void quant_tail_byte(const float* __restrict__ x,
                                float* __restrict__ vals,
                                unsigned char* __restrict__ idx8,
                                int start, int n) {
    int i = start + blockIdx.x * blockDim.x + threadIdx.x;
    if (i >= n) return;
    int q = quant_idx(x[i]);
    vals[i] = (float)q - 7.5f;
    idx8[i] = (unsigned char)q;
}

extern "C" void kernel_launch(void* const* d_in, const int* in_sizes, int n_in,
                              void* d_out, int out_size) {
    const float* X = (const float*)d_in[0];
    const int n  = in_sizes[0];               // 8,388,608
    const int n4 = n / 4;                     // 2,097,152 float4s
    const int rem = n - n4 * 4;

    const int BS = 256;

    if (out_size == 2 * n) {
        // float32 concat: [vals | idx-as-float]
        float* vals = (float*)d_out;
        float* idxf = vals + n;
        if (n4 > 0) {
            // ITER=4 per thread: threads = ceil(n4/4)
            int threads = (n4 + 3) / 4;
            int nb = (threads + BS - 1) / BS;  // 2048 CTAs for N=8M
            quant_float_concat_v2<<<nb, BS>>>((const float4*)X, (float4*)vals,
                                              (float4*)idxf, n4);
        }
        if (rem > 0)
            quant_tail_float<<<1, 32>>>(X, vals, idxf, n4 * 4, n);
    } else if (out_size == n) {
        float* vals = (float*)d_out;
        if (n4 > 0) {
            int nb = (n4 + BS - 1) / BS;
            quant_vals_only<<<nb, BS>>>((const float4*)X, (float4*)vals, n4);
        }
        if (rem > 0)
            quant_tail_float<<<1, 32>>>(X, vals, nullptr, n4 * 4, n);
    } else {
        float* vals = (float*)d_out;
        unsigned char* idx8 = (unsigned char*)d_out + (size_t)4 * n;
        if (n4 > 0) {
            int nb = (n4 + BS - 1) / BS;
            quant_byte_concat<<<nb, BS>>>((const float4*)X, (float4*)vals,
                                          (uchar4*)idx8, n4);
        }
        if (rem > 0)
            quant_tail_byte<<<1, 32>>>(X, vals, idx8, n4 * 4, n);
    }
}